// round 1
// baseline (speedup 1.0000x reference)
#include <cuda_runtime.h>

constexpr int NDRUG = 50000;
constexpr int NGENE = 50000;
constexpr int DHID  = 64;
constexpr int DEMB  = 32;

// Scratch (device globals — no allocation allowed)
__device__ float g_tm[4][NDRUG * DHID];   // transformed src features per relation
__device__ float g_acc[4][NDRUG * DHID];  // per-relation segment-sum accumulators
__device__ float g_h[2][NDRUG * DHID];    // hidden layer outputs (hd, hg)
__device__ float g_deg[4][NDRUG];         // per-relation in-degree of dst nodes

// ---------------------------------------------------------------------------
// degree histogram
// ---------------------------------------------------------------------------
__global__ void degree_kernel(const int* __restrict__ dst, float* __restrict__ deg, int E) {
    int i = blockIdx.x * blockDim.x + threadIdx.x;
    if (i < E) atomicAdd(&deg[dst[i]], 1.0f);
}

// ---------------------------------------------------------------------------
// Tiled fp32 GEMM: Y[M,N] = X[M,K] @ W[K,N]
// BM=128, full-N block, BK=32, 256 threads, thread tile TM=8 x TN=N/16
// ---------------------------------------------------------------------------
template<int K, int N>
__launch_bounds__(256)
__global__ void gemm_kernel(const float* __restrict__ X, const float* __restrict__ W,
                            float* __restrict__ Y, int M) {
    constexpr int BM = 128, BK = 32;
    constexpr int TM = 8, TN = N / 16;
    __shared__ float Xs[BM][BK + 4];
    __shared__ float Ws[BK][N + 4];
    const int tid  = threadIdx.x;
    const int trow = tid >> 4;      // 0..15
    const int tcol = tid & 15;      // 0..15
    const int m0   = blockIdx.x * BM;

    float acc[TM][TN];
#pragma unroll
    for (int i = 0; i < TM; i++)
#pragma unroll
        for (int j = 0; j < TN; j++) acc[i][j] = 0.f;

    for (int k0 = 0; k0 < K; k0 += BK) {
        // load X tile (128 x 32 floats) via float4, 4 per thread
#pragma unroll
        for (int i = 0; i < 4; i++) {
            int lin = tid + i * 256;        // float4 index, 0..1023
            int r   = lin >> 3;             // 8 float4 per row
            int c4  = (lin & 7) * 4;
            int gr  = m0 + r;
            float4 v = make_float4(0.f, 0.f, 0.f, 0.f);
            if (gr < M) v = *(const float4*)(X + (size_t)gr * K + k0 + c4);
            Xs[r][c4 + 0] = v.x; Xs[r][c4 + 1] = v.y;
            Xs[r][c4 + 2] = v.z; Xs[r][c4 + 3] = v.w;
        }
        // load W tile (32 x N floats)
        constexpr int WF4 = BK * N / 4;
#pragma unroll
        for (int i = 0; i < (WF4 + 255) / 256; i++) {
            int lin = tid + i * 256;
            if (lin < WF4) {
                int r  = lin / (N / 4);
                int c4 = (lin % (N / 4)) * 4;
                float4 v = *(const float4*)(W + (size_t)(k0 + r) * N + c4);
                Ws[r][c4 + 0] = v.x; Ws[r][c4 + 1] = v.y;
                Ws[r][c4 + 2] = v.z; Ws[r][c4 + 3] = v.w;
            }
        }
        __syncthreads();
#pragma unroll
        for (int k = 0; k < BK; k++) {
            float a[TM], b[TN];
#pragma unroll
            for (int i = 0; i < TM; i++) a[i] = Xs[trow * TM + i][k];
#pragma unroll
            for (int j = 0; j < TN; j++) b[j] = Ws[k][tcol * TN + j];
#pragma unroll
            for (int i = 0; i < TM; i++)
#pragma unroll
                for (int j = 0; j < TN; j++) acc[i][j] += a[i] * b[j];
        }
        __syncthreads();
    }
#pragma unroll
    for (int i = 0; i < TM; i++) {
        int gr = m0 + trow * TM + i;
        if (gr < M) {
#pragma unroll
            for (int j = 0; j < TN; j++)
                Y[(size_t)gr * N + tcol * TN + j] = acc[i][j];
        }
    }
}

// ---------------------------------------------------------------------------
// Edge scatter: acc[dst[e]] += m[src[e]]   (float4 chunks, atomicAdd)
// ---------------------------------------------------------------------------
template<int D>
__global__ void scatter_kernel(const float* __restrict__ m, const int* __restrict__ src,
                               const int* __restrict__ dst, float* __restrict__ acc, int E) {
    constexpr int C = D / 4;
    int idx = blockIdx.x * blockDim.x + threadIdx.x;
    if (idx >= E * C) return;
    int e = idx / C;
    int c = idx % C;
    int s = src[e];
    int d = dst[e];
    float4 v = *(const float4*)(m + (size_t)s * D + c * 4);
    float* o = acc + (size_t)d * D + c * 4;
    atomicAdd(o + 0, v.x);
    atomicAdd(o + 1, v.y);
    atomicAdd(o + 2, v.z);
    atomicAdd(o + 3, v.w);
}

// ---------------------------------------------------------------------------
// Combine: out = accA/max(degA,1) + accB/max(degB,1) + bias  (optional relu)
// ---------------------------------------------------------------------------
template<int D, bool RELU>
__global__ void combine_kernel(const float* __restrict__ accA, const float* __restrict__ degA,
                               const float* __restrict__ accB, const float* __restrict__ degB,
                               const float* __restrict__ bias, float* __restrict__ out, int n) {
    constexpr int C = D / 4;
    int idx = blockIdx.x * blockDim.x + threadIdx.x;
    if (idx >= n * C) return;
    int node = idx / C;
    int c    = idx % C;
    float ia = 1.0f / fmaxf(degA[node], 1.0f);
    float ib = 1.0f / fmaxf(degB[node], 1.0f);
    float4 a  = ((const float4*)accA)[idx];
    float4 b  = ((const float4*)accB)[idx];
    float4 bs = *(const float4*)(bias + c * 4);
    float4 r;
    r.x = a.x * ia + b.x * ib + bs.x;
    r.y = a.y * ia + b.y * ib + bs.y;
    r.z = a.z * ia + b.z * ib + bs.z;
    r.w = a.w * ia + b.w * ib + bs.w;
    if (RELU) {
        r.x = fmaxf(r.x, 0.f); r.y = fmaxf(r.y, 0.f);
        r.z = fmaxf(r.z, 0.f); r.w = fmaxf(r.w, 0.f);
    }
    ((float4*)out)[idx] = r;
}

// ---------------------------------------------------------------------------
// Orchestration
// Relations: 0=dd (drug->drug), 1=dg (drug->gene), 2=gd (gene->drug), 3=gg
//   hd = mean_dd + mean_gd + b_drug ; hg = mean_dg + mean_gg + b_gene
// ---------------------------------------------------------------------------
extern "C" void kernel_launch(void* const* d_in, const int* in_sizes, int n_in,
                              void* d_out, int out_size) {
    const float* xd = (const float*)d_in[0];
    const float* xg = (const float*)d_in[1];
    const int* es[8];
    for (int i = 0; i < 8; i++) es[i] = (const int*)d_in[2 + i];
    // es: 0=dd_src 1=dd_dst 2=dg_src 3=dg_dst 4=gd_src 5=gd_dst 6=gg_src 7=gg_dst
    const float* W1[4] = {(const float*)d_in[10], (const float*)d_in[11],
                          (const float*)d_in[12], (const float*)d_in[13]};
    const float* b1d = (const float*)d_in[14];
    const float* b1g = (const float*)d_in[15];
    const float* W2[4] = {(const float*)d_in[16], (const float*)d_in[17],
                          (const float*)d_in[18], (const float*)d_in[19]};
    const float* b2d = (const float*)d_in[20];
    const float* b2g = (const float*)d_in[21];
    float* out = (float*)d_out;
    const int E = in_sizes[2];

    float *tm, *acc, *h, *deg;
    cudaGetSymbolAddress((void**)&tm,  g_tm);
    cudaGetSymbolAddress((void**)&acc, g_acc);
    cudaGetSymbolAddress((void**)&h,   g_h);
    cudaGetSymbolAddress((void**)&deg, g_deg);

    const int TB = 256;
    const int gblk = (NDRUG + 127) / 128;

    // --- degrees (shared by both layers) ---
    cudaMemsetAsync(deg, 0, sizeof(float) * 4 * NDRUG, 0);
    for (int r = 0; r < 4; r++)
        degree_kernel<<<(E + TB - 1) / TB, TB>>>(es[2 * r + 1], deg + r * NDRUG, E);

    // --- layer 1: D_IN=128 -> D_HID=64, relu ---
    cudaMemsetAsync(acc, 0, sizeof(float) * 4 * NDRUG * DHID, 0);
    const float* src1[4] = {xd, xd, xg, xg};
    for (int r = 0; r < 4; r++)
        gemm_kernel<128, 64><<<gblk, 256>>>(src1[r], W1[r], tm + (size_t)r * NDRUG * DHID, NDRUG);
    {
        int n = E * (DHID / 4);
        for (int r = 0; r < 4; r++)
            scatter_kernel<64><<<(n + TB - 1) / TB, TB>>>(
                tm + (size_t)r * NDRUG * DHID, es[2 * r], es[2 * r + 1],
                acc + (size_t)r * NDRUG * DHID, E);
    }
    {
        int n = NDRUG * (DHID / 4);
        combine_kernel<64, true><<<(n + TB - 1) / TB, TB>>>(
            acc + (size_t)0 * NDRUG * DHID, deg + 0 * NDRUG,
            acc + (size_t)2 * NDRUG * DHID, deg + 2 * NDRUG, b1d, h, NDRUG);
        combine_kernel<64, true><<<(n + TB - 1) / TB, TB>>>(
            acc + (size_t)1 * NDRUG * DHID, deg + 1 * NDRUG,
            acc + (size_t)3 * NDRUG * DHID, deg + 3 * NDRUG, b1g,
            h + (size_t)NDRUG * DHID, NGENE);
    }

    // --- layer 2: D_HID=64 -> D_EMB=32, no relu ---
    cudaMemsetAsync(acc, 0, sizeof(float) * 4 * NDRUG * DEMB, 0);
    const float* hd = h;
    const float* hg = h + (size_t)NDRUG * DHID;
    const float* src2[4] = {hd, hd, hg, hg};
    for (int r = 0; r < 4; r++)
        gemm_kernel<64, 32><<<gblk, 256>>>(src2[r], W2[r], tm + (size_t)r * NDRUG * DEMB, NDRUG);
    {
        int n = E * (DEMB / 4);
        for (int r = 0; r < 4; r++)
            scatter_kernel<32><<<(n + TB - 1) / TB, TB>>>(
                tm + (size_t)r * NDRUG * DEMB, es[2 * r], es[2 * r + 1],
                acc + (size_t)r * NDRUG * DEMB, E);
    }
    {
        int n = NDRUG * (DEMB / 4);
        combine_kernel<32, false><<<(n + TB - 1) / TB, TB>>>(
            acc + (size_t)0 * NDRUG * DEMB, deg + 0 * NDRUG,
            acc + (size_t)2 * NDRUG * DEMB, deg + 2 * NDRUG, b2d, out, NDRUG);
        combine_kernel<32, false><<<(n + TB - 1) / TB, TB>>>(
            acc + (size_t)1 * NDRUG * DEMB, deg + 1 * NDRUG,
            acc + (size_t)3 * NDRUG * DEMB, deg + 3 * NDRUG, b2g,
            out + (size_t)NDRUG * DEMB, NGENE);
    }
}